// round 7
// baseline (speedup 1.0000x reference)
#include <cuda_runtime.h>
#include <cuda_bf16.h>
#include <cstdint>
#include <math.h>

#define BN 512
#define CC 3
#define NP 49
#define NT 76
#define DD 768
#define EPSI 0.1f
#define THRESH 0.01f
#define MAX_ITER 100

#define NBLK 128          // sinkhorn persistent blocks (must be <= SM count)
#define STPB 512          // sinkhorn threads per block
#define SKP (49*77)       // padded K tile stride (3773 floats)

// ------------------------- device scratch (no allocs allowed) ----------------
__device__ float g_K[(size_t)CC*BN*NP*NT];        // exp kernel per (c,b)
__device__ float g_L[(size_t)BN*BN];              // logits_per_image
__device__ float g_lse_row[BN];
__device__ float g_lse_col[BN];
__device__ float4 g_err4[NBLK];
__device__ float g_ot_part[NBLK];
__device__ unsigned g_count;
__device__ unsigned g_gen;
__device__ unsigned g_mask;
__device__ unsigned g_iter[3];

// ------------------------------ init ----------------------------------------
__global__ void init_state_kernel() {
    g_count = 0u;
    g_gen = 0u;
    g_mask = 7u;
    g_iter[0] = 0u; g_iter[1] = 0u; g_iter[2] = 0u;
}

// --------------------- sim + K kernel (bf16 tensor cores) --------------------
// One block per (b,c). M=64 (49 real) x N=80 (76 real) x K=768.
// 8 warps: 4 (m) x 2 (n); each warp: 1 m16 tile x 5 n8 frags, mma.m16n8k16 bf16.
// fp32 -> bf16 conversion fused into smem fill; row norms accumulated in the
// same pass (deterministic fixed-owner accumulation). GMEM loads for chunk
// kc+1 are prefetched into registers before the chunk-kc MMA block.

__device__ __forceinline__ uint32_t pack_bf16(float x, float y) {
    __nv_bfloat162 h = __floats2bfloat162_rn(x, y);  // .x = x in low 16 bits
    return *reinterpret_cast<uint32_t*>(&h);
}

__global__ void __launch_bounds__(256) simK_kernel(const float* __restrict__ li,
                                                   const float* __restrict__ lt) {
    // padded bf16 tiles as 32-bit words; row stride 20 words (16 data + 4 pad)
    __shared__ uint32_t As32[64*20];
    __shared__ uint32_t Bs32[80*20];
    __shared__ float normA[64];
    __shared__ float normB[80];

    const int blk = blockIdx.x;        // b*3 + c
    const int b = blk / 3;
    const int c = blk - b*3;
    const float4* A4 = reinterpret_cast<const float4*>(li + ((size_t)(b*CC + c))*NP*DD);
    const float4* B4 = reinterpret_cast<const float4*>(lt + ((size_t)(b*CC + c))*NT*DD);

    const int t = threadIdx.x;
    const int lane = t & 31;
    const int w = t >> 5;
    const int gid = lane >> 2;          // 0..7
    const int tig = lane & 3;           // 0..3

    // fill roles: threads 0..97 -> A (row = t/2, half = t&1)
    //             threads 104..255 -> B (tb = t-104, row = tb/2, half = tb&1)
    const bool isA = (t < 98);
    const bool isB = (t >= 104);
    const int arow = t >> 1;
    const int tb = t - 104;
    const int brow = tb >> 1;
    const int q0A = (t & 1) * 4;
    const int q0B = (tb & 1) * 4;

    // zero norms + pad rows (pad rows written once; never overwritten)
    if (t < 64) normA[t] = 0.f;
    if (t >= 64 && t < 144) normB[t - 64] = 0.f;
    for (int e = t; e < (15 + 4) * 16; e += 256) {
        int rr = e >> 4, ww = e & 15;
        if (rr < 15) As32[(49 + rr)*20 + ww] = 0u;
        else         Bs32[(76 + (rr - 15))*20 + ww] = 0u;
    }

    // warp tiling
    const int wm = w >> 1;              // 0..3
    const int wn = w & 1;               // 0..1
    const int r0 = wm*16 + gid;
    const int r1 = r0 + 8;

    float acc[5][4];
    #pragma unroll
    for (int f = 0; f < 5; f++) {
        acc[f][0] = 0.f; acc[f][1] = 0.f; acc[f][2] = 0.f; acc[f][3] = 0.f;
    }

    float4 rv[4];
    auto issue_load = [&](int kc) {
        if (isA) {
            const float4* src = A4 + arow*192 + kc*8 + q0A;
            #pragma unroll
            for (int i = 0; i < 4; i++) rv[i] = src[i];
        } else if (isB) {
            const float4* src = B4 + brow*192 + kc*8 + q0B;
            #pragma unroll
            for (int i = 0; i < 4; i++) rv[i] = src[i];
        }
    };

    issue_load(0);

    for (int kc = 0; kc < 24; kc++) {
        __syncthreads();   // previous compute done reading smem (and pads ready)
        // ---- store prefetched regs: bf16 convert + sum-of-squares ----
        float ss = 0.f;
        if (isA) {
            #pragma unroll
            for (int i = 0; i < 4; i++) {
                float4 v = rv[i];
                ss += v.x*v.x + v.y*v.y + v.z*v.z + v.w*v.w;
                int wbase = arow*20 + (q0A + i)*2;
                As32[wbase]     = pack_bf16(v.x, v.y);
                As32[wbase + 1] = pack_bf16(v.z, v.w);
            }
        } else if (isB) {
            #pragma unroll
            for (int i = 0; i < 4; i++) {
                float4 v = rv[i];
                ss += v.x*v.x + v.y*v.y + v.z*v.z + v.w*v.w;
                int wbase = brow*20 + (q0B + i)*2;
                Bs32[wbase]     = pack_bf16(v.x, v.y);
                Bs32[wbase + 1] = pack_bf16(v.z, v.w);
            }
        }
        ss += __shfl_xor_sync(0xffffffffu, ss, 1);   // pair halves of each row
        if (isA && (t & 1) == 0) normA[arow] += ss;  // single fixed owner -> deterministic
        if (isB && (tb & 1) == 0) normB[brow] += ss;
        __syncthreads();

        // prefetch next chunk (no smem dependency until next store)
        if (kc < 23) issue_load(kc + 1);

        // ---- compute: 2 k16 steps per chunk ----
        #pragma unroll
        for (int ks = 0; ks < 2; ks++) {
            const int kw = ks * 8;
            uint32_t a0 = As32[r0*20 + kw + tig];
            uint32_t a1 = As32[r1*20 + kw + tig];
            uint32_t a2 = As32[r0*20 + kw + 4 + tig];
            uint32_t a3 = As32[r1*20 + kw + 4 + tig];
            #pragma unroll
            for (int f = 0; f < 5; f++) {
                int n = wn*40 + f*8 + gid;
                uint32_t b0 = Bs32[n*20 + kw + tig];
                uint32_t b1 = Bs32[n*20 + kw + 4 + tig];
                asm volatile(
                    "mma.sync.aligned.m16n8k16.row.col.f32.bf16.bf16.f32 "
                    "{%0,%1,%2,%3}, {%4,%5,%6,%7}, {%8,%9}, {%0,%1,%2,%3};"
                    : "+f"(acc[f][0]), "+f"(acc[f][1]), "+f"(acc[f][2]), "+f"(acc[f][3])
                    : "r"(a0), "r"(a1), "r"(a2), "r"(a3), "r"(b0), "r"(b1));
            }
        }
    }

    // ---- norms -> inverse norms (in place) ----
    __syncthreads();
    if (t < 64)                normA[t]      = 1.0f / fmaxf(sqrtf(normA[t]), 1e-12f);
    if (t >= 64 && t < 144)    normB[t - 64] = 1.0f / fmaxf(sqrtf(normB[t - 64]), 1e-12f);
    __syncthreads();

    // ---- epilogue: sim -> K ----
    const size_t base = (size_t)(c*BN + b) * (NP*NT);
    const float ia0 = (r0 < NP) ? normA[r0] : 0.f;
    const float ia1 = (r1 < NP) ? normA[r1] : 0.f;
    #pragma unroll
    for (int f = 0; f < 5; f++) {
        int col = wn*40 + f*8 + tig*2;
        float ib0 = normB[col];
        float ib1 = normB[col + 1];
        if (col < NT) {
            if (r0 < NP) {
                float s0 = acc[f][0] * ia0 * ib0;
                float s1 = acc[f][1] * ia0 * ib1;
                g_K[base + (size_t)r0*NT + col] = expf(fmaf(10.0f, s0, -10.0f));
                if (col + 1 < NT)
                    g_K[base + (size_t)r0*NT + col + 1] = expf(fmaf(10.0f, s1, -10.0f));
            }
            if (r1 < NP) {
                float s2 = acc[f][2] * ia1 * ib0;
                float s3 = acc[f][3] * ia1 * ib1;
                g_K[base + (size_t)r1*NT + col] = expf(fmaf(10.0f, s2, -10.0f));
                if (col + 1 < NT)
                    g_K[base + (size_t)r1*NT + col + 1] = expf(fmaf(10.0f, s3, -10.0f));
            }
        }
    }
}

// ------------------------- persistent Sinkhorn kernel ------------------------
// 128 blocks, each owns 4 batches x 3 channels fully in smem. Per-channel
// global convergence via one sense-reversing barrier per iteration.
// Cross-block state (g_err4/g_mask/g_iter) uses L2-coherent accesses.
extern __shared__ float sh[];
__global__ void __launch_bounds__(STPB) sinkhorn_kernel() {
    float* sK  = sh;                       // 12*SKP
    float* r_s = sK + 12*SKP;              // 12*52
    float* c_s = r_s + 12*52;              // 12*80
    float* red = c_s + 12*80;              // 3*STPB
    __shared__ unsigned s_mask;

    const int tid = threadIdx.x;
    const int blk = blockIdx.x;

    // load K tiles (padded stride 77)
    for (int p = 0; p < 12; p++) {
        int ch = p >> 2;
        int b  = blk*4 + (p & 3);
        const float* src = g_K + (size_t)(ch*BN + b) * (NP*NT);
        for (int e = tid; e < NP*NT; e += STPB) {
            int n = e / NT, m = e - n*NT;
            sK[p*SKP + n*77 + m] = src[e];
        }
    }
    for (int e = tid; e < 12*52; e += STPB) r_s[e] = 1.0f;
    for (int e = tid; e < 12*80; e += STPB) c_s[e] = 1.0f;
    if (tid == 0) s_mask = 7u;
    __syncthreads();

    unsigned gen = 0;
    unsigned mask = 7u;
    const float U = 1.0f / (float)NP;
    const float V = 1.0f / (float)NT;

    while (mask) {
        float e0 = 0.f, e1 = 0.f, e2 = 0.f;
        // r update: r = u / (K c)   (also accumulates |r_new - r_old|)
        for (int idx = tid; idx < 12*NP; idx += STPB) {
            int p = idx / NP, n = idx - p*NP;
            int ch = p >> 2;
            if (mask & (1u << ch)) {
                const float* Kr = &sK[p*SKP + n*77];
                const float* cp = &c_s[p*80];
                float s = 0.f;
                #pragma unroll 4
                for (int m = 0; m < NT; m++) s = fmaf(Kr[m], cp[m], s);
                float rn = U / s;
                float d = fabsf(rn - r_s[p*52 + n]);
                if (ch == 0) e0 += d; else if (ch == 1) e1 += d; else e2 += d;
                r_s[p*52 + n] = rn;
            }
        }
        __syncthreads();
        // c update: c = v / (K^T r)
        for (int idx = tid; idx < 12*NT; idx += STPB) {
            int p = idx / NT, m = idx - p*NT;
            int ch = p >> 2;
            if (mask & (1u << ch)) {
                const float* Kc = &sK[p*SKP + m];
                const float* rp = &r_s[p*52];
                float s = 0.f;
                #pragma unroll 7
                for (int n = 0; n < NP; n++) s = fmaf(Kc[n*77], rp[n], s);
                c_s[p*80 + m] = V / s;
            }
        }
        // deterministic block reduction of the 3 error partials
        red[tid] = e0; red[STPB + tid] = e1; red[2*STPB + tid] = e2;
        __syncthreads();
        for (int st = STPB/2; st > 0; st >>= 1) {
            if (tid < st) {
                red[tid]          += red[tid + st];
                red[STPB + tid]   += red[STPB + tid + st];
                red[2*STPB + tid] += red[2*STPB + tid + st];
            }
            __syncthreads();
        }
        if (tid == 0) {
            g_err4[blk] = make_float4(red[0], red[STPB], red[2*STPB], 0.f);
            __threadfence();
            unsigned my = atomicAdd(&g_count, 1u);
            gen++;
            if (my == NBLK - 1) {
                // master: reduce errors, advance per-channel state
                __threadfence();
                float s0 = 0.f, s1 = 0.f, s2 = 0.f;
                #pragma unroll 8
                for (int i2 = 0; i2 < NBLK; i2++) {
                    float4 e4 = __ldcg(&g_err4[i2]);
                    s0 += e4.x; s1 += e4.y; s2 += e4.z;
                }
                unsigned om;
                asm volatile("ld.acquire.gpu.u32 %0, [%1];" : "=r"(om) : "l"(&g_mask));
                unsigned nm = om;
                float es[3] = {s0, s1, s2};
                for (int ch = 0; ch < 3; ch++) {
                    if (om & (1u << ch)) {
                        float err = es[ch] * (1.0f / (float)(BN*NP));
                        unsigned it = atomicAdd(&g_iter[ch], 1u) + 1u;
                        if (!(it < MAX_ITER && err >= THRESH)) nm &= ~(1u << ch);
                    }
                }
                atomicExch(&g_mask, nm);
                g_count = 0u;
                __threadfence();
                atomicAdd(&g_gen, 1u);
            } else {
                unsigned cur;
                do {
                    asm volatile("ld.acquire.gpu.u32 %0, [%1];" : "=r"(cur) : "l"(&g_gen));
                    if (cur < gen) __nanosleep(64);
                } while (cur < gen);
            }
            unsigned mk;
            asm volatile("ld.acquire.gpu.u32 %0, [%1];" : "=r"(mk) : "l"(&g_mask));
            s_mask = mk;
        }
        __syncthreads();
        mask = s_mask;
    }

    // OT contribution: sum r*c*K*sim with sim = 1 + eps*log(K)
    float ot = 0.f;
    for (int p = 0; p < 12; p++) {
        const float* Kp = &sK[p*SKP];
        const float* rp = &r_s[p*52];
        const float* cp = &c_s[p*80];
        for (int e = tid; e < NP*NT; e += STPB) {
            int n = e / NT, m = e - n*NT;
            float Kv = Kp[n*77 + m];
            float simv = fmaf(EPSI, logf(Kv), 1.0f);
            ot = fmaf(rp[n]*cp[m], Kv*simv, ot);
        }
    }
    red[tid] = ot;
    __syncthreads();
    for (int st = STPB/2; st > 0; st >>= 1) {
        if (tid < st) red[tid] += red[tid + st];
        __syncthreads();
    }
    if (tid == 0) g_ot_part[blk] = red[0];
}

// ---------------- logits GEMM: 512x512x2304, tf32 tensor cores ---------------
// 64 blocks of 64x64 tiles, full K. 8 warps (4m x 2n), warp tile m16n32 via
// 4 n8 fragments, mma.m16n8k8 tf32. Scale/3 folded into epilogue -> g_L.
__device__ __forceinline__ uint32_t f2tf(float x) {
    uint32_t r;
    asm("cvt.rna.tf32.f32 %0, %1;" : "=r"(r) : "f"(x));
    return r;
}

__global__ void __launch_bounds__(256) gemm_logits_tf32_kernel(
        const float* __restrict__ img, const float* __restrict__ txt,
        const float* __restrict__ scale_p) {
    __shared__ uint32_t As[64*36];   // [row][k], stride 36 words
    __shared__ uint32_t Bs[64*36];
    const int bx = blockIdx.x, by = blockIdx.y;
    const int t = threadIdx.x;
    const int lane = t & 31, w = t >> 5;
    const int gid = lane >> 2, tig = lane & 3;
    const int wm = w >> 1, wn = w & 1;
    const int rowA = by * 64, rowB = bx * 64;
    const float4* A4 = reinterpret_cast<const float4*>(img);
    const float4* B4 = reinterpret_cast<const float4*>(txt);
    const int lr = t >> 2;       // 0..63 row within tile
    const int lj = t & 3;        // 0..3  k-quarter

    float acc[4][4];
    #pragma unroll
    for (int f = 0; f < 4; f++) {
        acc[f][0] = 0.f; acc[f][1] = 0.f; acc[f][2] = 0.f; acc[f][3] = 0.f;
    }

    for (int kc = 0; kc < 72; kc++) {
        __syncthreads();
        {
            const size_t offA = (size_t)(rowA + lr)*576 + kc*8 + lj*2;
            const size_t offB = (size_t)(rowB + lr)*576 + kc*8 + lj*2;
            float4 va0 = A4[offA], va1 = A4[offA + 1];
            float4 vb0 = B4[offB], vb1 = B4[offB + 1];
            uint4* pa = reinterpret_cast<uint4*>(&As[lr*36 + lj*8]);
            uint4* pb = reinterpret_cast<uint4*>(&Bs[lr*36 + lj*8]);
            pa[0] = make_uint4(f2tf(va0.x), f2tf(va0.y), f2tf(va0.z), f2tf(va0.w));
            pa[1] = make_uint4(f2tf(va1.x), f2tf(va1.y), f2tf(va1.z), f2tf(va1.w));
            pb[0] = make_uint4(f2tf(vb0.x), f2tf(vb0.y), f2tf(vb0.z), f2tf(vb0.w));
            pb[1] = make_uint4(f2tf(vb1.x), f2tf(vb1.y), f2tf(vb1.z), f2tf(vb1.w));
        }
        __syncthreads();
        #pragma unroll
        for (int ks = 0; ks < 4; ks++) {
            const int kw = ks * 8;
            uint32_t a0 = As[(wm*16 + gid)*36 + kw + tig];
            uint32_t a1 = As[(wm*16 + gid + 8)*36 + kw + tig];
            uint32_t a2 = As[(wm*16 + gid)*36 + kw + 4 + tig];
            uint32_t a3 = As[(wm*16 + gid + 8)*36 + kw + 4 + tig];
            #pragma unroll
            for (int f = 0; f < 4; f++) {
                int col = wn*32 + f*8 + gid;
                uint32_t b0 = Bs[col*36 + kw + tig];
                uint32_t b1 = Bs[col*36 + kw + 4 + tig];
                asm volatile(
                    "mma.sync.aligned.m16n8k8.row.col.f32.tf32.tf32.f32 "
                    "{%0,%1,%2,%3}, {%4,%5,%6,%7}, {%8,%9}, {%0,%1,%2,%3};"
                    : "+f"(acc[f][0]), "+f"(acc[f][1]), "+f"(acc[f][2]), "+f"(acc[f][3])
                    : "r"(a0), "r"(a1), "r"(a2), "r"(a3), "r"(b0), "r"(b1));
            }
        }
    }

    const float s = scale_p[0] * (1.0f / (float)CC);
    const int r0 = rowA + wm*16 + gid;
    #pragma unroll
    for (int f = 0; f < 4; f++) {
        int col = rowB + wn*32 + f*8 + tig*2;
        float2 v0 = make_float2(acc[f][0]*s, acc[f][1]*s);
        float2 v1 = make_float2(acc[f][2]*s, acc[f][3]*s);
        *reinterpret_cast<float2*>(&g_L[(size_t)r0*BN + col]) = v0;
        *reinterpret_cast<float2*>(&g_L[(size_t)(r0 + 8)*BN + col]) = v1;
    }
}

// --------------------------- LSE + finalize ----------------------------------
__global__ void row_lse_kernel() {
    __shared__ float red[256];
    const int b = blockIdx.x, t = threadIdx.x;
    const float* row = g_L + (size_t)b * BN;
    float x0 = row[t], x1 = row[t + 256];
    red[t] = fmaxf(x0, x1);
    __syncthreads();
    for (int st = 128; st > 0; st >>= 1) {
        if (t < st) red[t] = fmaxf(red[t], red[t + st]);
        __syncthreads();
    }
    float M = red[0];
    __syncthreads();
    red[t] = expf(x0 - M) + expf(x1 - M);
    __syncthreads();
    for (int st = 128; st > 0; st >>= 1) {
        if (t < st) red[t] += red[t + st];
        __syncthreads();
    }
    if (t == 0) g_lse_row[b] = M + logf(red[0]);
}

__global__ void col_lse_kernel() {
    __shared__ float red[256];
    const int b = blockIdx.x, t = threadIdx.x;
    float x0 = g_L[(size_t)t * BN + b], x1 = g_L[(size_t)(t + 256) * BN + b];
    red[t] = fmaxf(x0, x1);
    __syncthreads();
    for (int st = 128; st > 0; st >>= 1) {
        if (t < st) red[t] = fmaxf(red[t], red[t + st]);
        __syncthreads();
    }
    float M = red[0];
    __syncthreads();
    red[t] = expf(x0 - M) + expf(x1 - M);
    __syncthreads();
    for (int st = 128; st > 0; st >>= 1) {
        if (t < st) red[t] += red[t + st];
        __syncthreads();
    }
    if (t == 0) g_lse_col[b] = M + logf(red[0]);
}

__global__ void finalize_kernel(float* __restrict__ out) {
    __shared__ float r1[512], r2[512], r3[512];
    const int t = threadIdx.x;
    float diag = g_L[(size_t)t * BN + t];
    r1[t] = g_lse_row[t] - diag;
    r2[t] = g_lse_col[t] - diag;
    r3[t] = (t < NBLK) ? g_ot_part[t] : 0.f;
    __syncthreads();
    for (int st = 256; st > 0; st >>= 1) {
        if (t < st) { r1[t] += r1[t+st]; r2[t] += r2[t+st]; r3[t] += r3[t+st]; }
        __syncthreads();
    }
    if (t == 0)
        out[0] = (r1[0] + r2[0]) * (0.5f / (float)BN) + r3[0];
}

// ------------------------------- launch --------------------------------------
extern "C" void kernel_launch(void* const* d_in, const int* in_sizes, int n_in,
                              void* d_out, int out_size) {
    (void)in_sizes; (void)n_in; (void)out_size;
    const float* img   = (const float*)d_in[0];
    const float* txt   = (const float*)d_in[1];
    const float* scale = (const float*)d_in[2];
    const float* li    = (const float*)d_in[3];
    const float* lt    = (const float*)d_in[4];
    float* out = (float*)d_out;

    const size_t sk_smem = (size_t)(12*SKP + 12*52 + 12*80 + 3*STPB) * sizeof(float);
    cudaFuncSetAttribute(sinkhorn_kernel,
                         cudaFuncAttributeMaxDynamicSharedMemorySize, (int)sk_smem);

    init_state_kernel<<<1, 1>>>();
    simK_kernel<<<BN*CC, 256>>>(li, lt);
    sinkhorn_kernel<<<NBLK, STPB, sk_smem>>>();
    dim3 gg(8, 8);
    gemm_logits_tf32_kernel<<<gg, 256>>>(img, txt, scale);
    row_lse_kernel<<<BN, 256>>>();
    col_lse_kernel<<<BN, 256>>>();
    finalize_kernel<<<1, 512>>>(out);
}

// round 8
// speedup vs baseline: 1.2682x; 1.2682x over previous
#include <cuda_runtime.h>
#include <cuda_bf16.h>
#include <cstdint>
#include <math.h>

#define BN 512
#define CC 3
#define NP 49
#define NT 76
#define DD 768
#define EPSI 0.1f
#define THRESH 0.01f
#define MAX_ITER 100

#define NBLK 128          // sinkhorn persistent blocks (must be <= SM count)
#define STPB 512          // sinkhorn threads per block
#define SKP (49*77)       // padded K tile stride (3773 floats)
#define KSPLIT 6

// ------------------------- device scratch (no allocs allowed) ----------------
__device__ float g_K[(size_t)CC*BN*NP*NT];        // exp kernel per (c,b)
__device__ float g_Gp[(size_t)KSPLIT*BN*BN];      // split-K partials of logits GEMM
__device__ float g_L[(size_t)BN*BN];              // logits_per_image
__device__ float g_lse_row[BN];
__device__ float g_lse_col[BN];
__device__ float4 g_err4[NBLK];
__device__ float g_ot_part[NBLK];
__device__ unsigned g_count;
__device__ unsigned g_gen;
__device__ unsigned g_mask;
__device__ unsigned g_iter[3];

// ------------------------------ init ----------------------------------------
__global__ void init_state_kernel() {
    g_count = 0u;
    g_gen = 0u;
    g_mask = 7u;
    g_iter[0] = 0u; g_iter[1] = 0u; g_iter[2] = 0u;
}

// --------------------- sim + K kernel (bf16 tensor cores) --------------------
// One block per (b,c). M=64 (49 real) x N=80 (76 real) x K=768.
// 8 warps: 4 (m) x 2 (n); each warp: 1 m16 tile x 5 n8 frags, mma.m16n8k16 bf16.
// fp32 -> bf16 conversion fused into smem fill; row norms accumulated in the
// same pass (deterministic fixed-owner accumulation). GMEM loads for chunk
// kc+1 are prefetched into registers before the chunk-kc MMA block.

__device__ __forceinline__ uint32_t pack_bf16(float x, float y) {
    __nv_bfloat162 h = __floats2bfloat162_rn(x, y);  // .x = x in low 16 bits
    return *reinterpret_cast<uint32_t*>(&h);
}

__global__ void __launch_bounds__(256) simK_kernel(const float* __restrict__ li,
                                                   const float* __restrict__ lt) {
    // padded bf16 tiles as 32-bit words; row stride 20 words (16 data + 4 pad)
    __shared__ uint32_t As32[64*20];
    __shared__ uint32_t Bs32[80*20];
    __shared__ float normA[64];
    __shared__ float normB[80];

    const int blk = blockIdx.x;        // b*3 + c
    const int b = blk / 3;
    const int c = blk - b*3;
    const float4* A4 = reinterpret_cast<const float4*>(li + ((size_t)(b*CC + c))*NP*DD);
    const float4* B4 = reinterpret_cast<const float4*>(lt + ((size_t)(b*CC + c))*NT*DD);

    const int t = threadIdx.x;
    const int lane = t & 31;
    const int w = t >> 5;
    const int gid = lane >> 2;          // 0..7
    const int tig = lane & 3;           // 0..3

    // fill roles: threads 0..97 -> A (row = t/2, half = t&1)
    //             threads 104..255 -> B (tb = t-104, row = tb/2, half = tb&1)
    const bool isA = (t < 98);
    const bool isB = (t >= 104);
    const int arow = t >> 1;
    const int tb = t - 104;
    const int brow = tb >> 1;
    const int q0A = (t & 1) * 4;
    const int q0B = (tb & 1) * 4;

    // zero norms + pad rows (pad rows written once; never overwritten)
    if (t < 64) normA[t] = 0.f;
    if (t >= 64 && t < 144) normB[t - 64] = 0.f;
    for (int e = t; e < (15 + 4) * 16; e += 256) {
        int rr = e >> 4, ww = e & 15;
        if (rr < 15) As32[(49 + rr)*20 + ww] = 0u;
        else         Bs32[(76 + (rr - 15))*20 + ww] = 0u;
    }

    // warp tiling
    const int wm = w >> 1;              // 0..3
    const int wn = w & 1;               // 0..1
    const int r0 = wm*16 + gid;
    const int r1 = r0 + 8;

    float acc[5][4];
    #pragma unroll
    for (int f = 0; f < 5; f++) {
        acc[f][0] = 0.f; acc[f][1] = 0.f; acc[f][2] = 0.f; acc[f][3] = 0.f;
    }

    float4 rv[4];
    auto issue_load = [&](int kc) {
        if (isA) {
            const float4* src = A4 + arow*192 + kc*8 + q0A;
            #pragma unroll
            for (int i = 0; i < 4; i++) rv[i] = src[i];
        } else if (isB) {
            const float4* src = B4 + brow*192 + kc*8 + q0B;
            #pragma unroll
            for (int i = 0; i < 4; i++) rv[i] = src[i];
        }
    };

    issue_load(0);

    for (int kc = 0; kc < 24; kc++) {
        __syncthreads();   // previous compute done reading smem (and pads ready)
        // ---- store prefetched regs: bf16 convert + sum-of-squares ----
        float ss = 0.f;
        if (isA) {
            #pragma unroll
            for (int i = 0; i < 4; i++) {
                float4 v = rv[i];
                ss += v.x*v.x + v.y*v.y + v.z*v.z + v.w*v.w;
                int wbase = arow*20 + (q0A + i)*2;
                As32[wbase]     = pack_bf16(v.x, v.y);
                As32[wbase + 1] = pack_bf16(v.z, v.w);
            }
        } else if (isB) {
            #pragma unroll
            for (int i = 0; i < 4; i++) {
                float4 v = rv[i];
                ss += v.x*v.x + v.y*v.y + v.z*v.z + v.w*v.w;
                int wbase = brow*20 + (q0B + i)*2;
                Bs32[wbase]     = pack_bf16(v.x, v.y);
                Bs32[wbase + 1] = pack_bf16(v.z, v.w);
            }
        }
        ss += __shfl_xor_sync(0xffffffffu, ss, 1);   // pair halves of each row
        if (isA && (t & 1) == 0) normA[arow] += ss;  // single fixed owner -> deterministic
        if (isB && (tb & 1) == 0) normB[brow] += ss;
        __syncthreads();

        // prefetch next chunk (no smem dependency until next store)
        if (kc < 23) issue_load(kc + 1);

        // ---- compute: 2 k16 steps per chunk ----
        #pragma unroll
        for (int ks = 0; ks < 2; ks++) {
            const int kw = ks * 8;
            uint32_t a0 = As32[r0*20 + kw + tig];
            uint32_t a1 = As32[r1*20 + kw + tig];
            uint32_t a2 = As32[r0*20 + kw + 4 + tig];
            uint32_t a3 = As32[r1*20 + kw + 4 + tig];
            #pragma unroll
            for (int f = 0; f < 5; f++) {
                int n = wn*40 + f*8 + gid;
                uint32_t b0 = Bs32[n*20 + kw + tig];
                uint32_t b1 = Bs32[n*20 + kw + 4 + tig];
                asm volatile(
                    "mma.sync.aligned.m16n8k16.row.col.f32.bf16.bf16.f32 "
                    "{%0,%1,%2,%3}, {%4,%5,%6,%7}, {%8,%9}, {%0,%1,%2,%3};"
                    : "+f"(acc[f][0]), "+f"(acc[f][1]), "+f"(acc[f][2]), "+f"(acc[f][3])
                    : "r"(a0), "r"(a1), "r"(a2), "r"(a3), "r"(b0), "r"(b1));
            }
        }
    }

    // ---- norms -> inverse norms (in place) ----
    __syncthreads();
    if (t < 64)                normA[t]      = 1.0f / fmaxf(sqrtf(normA[t]), 1e-12f);
    if (t >= 64 && t < 144)    normB[t - 64] = 1.0f / fmaxf(sqrtf(normB[t - 64]), 1e-12f);
    __syncthreads();

    // ---- epilogue: sim -> K ----
    const size_t base = (size_t)(c*BN + b) * (NP*NT);
    const float ia0 = (r0 < NP) ? normA[r0] : 0.f;
    const float ia1 = (r1 < NP) ? normA[r1] : 0.f;
    #pragma unroll
    for (int f = 0; f < 5; f++) {
        int col = wn*40 + f*8 + tig*2;
        float ib0 = normB[col];
        float ib1 = normB[col + 1];
        if (col < NT) {
            if (r0 < NP) {
                float s0 = acc[f][0] * ia0 * ib0;
                float s1 = acc[f][1] * ia0 * ib1;
                g_K[base + (size_t)r0*NT + col] = expf(fmaf(10.0f, s0, -10.0f));
                if (col + 1 < NT)
                    g_K[base + (size_t)r0*NT + col + 1] = expf(fmaf(10.0f, s1, -10.0f));
            }
            if (r1 < NP) {
                float s2 = acc[f][2] * ia1 * ib0;
                float s3 = acc[f][3] * ia1 * ib1;
                g_K[base + (size_t)r1*NT + col] = expf(fmaf(10.0f, s2, -10.0f));
                if (col + 1 < NT)
                    g_K[base + (size_t)r1*NT + col + 1] = expf(fmaf(10.0f, s3, -10.0f));
            }
        }
    }
}

// ------------------------- persistent Sinkhorn kernel ------------------------
// 128 blocks, each owns 4 batches x 3 channels fully in smem. Per-channel
// global convergence via one sense-reversing barrier per iteration.
// Cross-block state (g_err4/g_mask/g_iter) uses L2-coherent accesses.
extern __shared__ float sh[];
__global__ void __launch_bounds__(STPB) sinkhorn_kernel() {
    float* sK  = sh;                       // 12*SKP
    float* r_s = sK + 12*SKP;              // 12*52
    float* c_s = r_s + 12*52;              // 12*80
    float* red = c_s + 12*80;              // 3*STPB
    __shared__ unsigned s_mask;

    const int tid = threadIdx.x;
    const int blk = blockIdx.x;

    // load K tiles (padded stride 77)
    for (int p = 0; p < 12; p++) {
        int ch = p >> 2;
        int b  = blk*4 + (p & 3);
        const float* src = g_K + (size_t)(ch*BN + b) * (NP*NT);
        for (int e = tid; e < NP*NT; e += STPB) {
            int n = e / NT, m = e - n*NT;
            sK[p*SKP + n*77 + m] = src[e];
        }
    }
    for (int e = tid; e < 12*52; e += STPB) r_s[e] = 1.0f;
    for (int e = tid; e < 12*80; e += STPB) c_s[e] = 1.0f;
    if (tid == 0) s_mask = 7u;
    __syncthreads();

    unsigned gen = 0;
    unsigned mask = 7u;
    const float U = 1.0f / (float)NP;
    const float V = 1.0f / (float)NT;

    while (mask) {
        float e0 = 0.f, e1 = 0.f, e2 = 0.f;
        // r update: r = u / (K c)   (also accumulates |r_new - r_old|)
        for (int idx = tid; idx < 12*NP; idx += STPB) {
            int p = idx / NP, n = idx - p*NP;
            int ch = p >> 2;
            if (mask & (1u << ch)) {
                const float* Kr = &sK[p*SKP + n*77];
                const float* cp = &c_s[p*80];
                float s = 0.f;
                #pragma unroll 4
                for (int m = 0; m < NT; m++) s = fmaf(Kr[m], cp[m], s);
                float rn = U / s;
                float d = fabsf(rn - r_s[p*52 + n]);
                if (ch == 0) e0 += d; else if (ch == 1) e1 += d; else e2 += d;
                r_s[p*52 + n] = rn;
            }
        }
        __syncthreads();
        // c update: c = v / (K^T r)
        for (int idx = tid; idx < 12*NT; idx += STPB) {
            int p = idx / NT, m = idx - p*NT;
            int ch = p >> 2;
            if (mask & (1u << ch)) {
                const float* Kc = &sK[p*SKP + m];
                const float* rp = &r_s[p*52];
                float s = 0.f;
                #pragma unroll 7
                for (int n = 0; n < NP; n++) s = fmaf(Kc[n*77], rp[n], s);
                c_s[p*80 + m] = V / s;
            }
        }
        // deterministic block reduction of the 3 error partials
        red[tid] = e0; red[STPB + tid] = e1; red[2*STPB + tid] = e2;
        __syncthreads();
        for (int st = STPB/2; st > 0; st >>= 1) {
            if (tid < st) {
                red[tid]          += red[tid + st];
                red[STPB + tid]   += red[STPB + tid + st];
                red[2*STPB + tid] += red[2*STPB + tid + st];
            }
            __syncthreads();
        }
        if (tid == 0) {
            g_err4[blk] = make_float4(red[0], red[STPB], red[2*STPB], 0.f);
            __threadfence();
            unsigned my = atomicAdd(&g_count, 1u);
            gen++;
            if (my == NBLK - 1) {
                // master: reduce errors, advance per-channel state
                __threadfence();
                float s0 = 0.f, s1 = 0.f, s2 = 0.f;
                #pragma unroll 8
                for (int i2 = 0; i2 < NBLK; i2++) {
                    float4 e4 = __ldcg(&g_err4[i2]);
                    s0 += e4.x; s1 += e4.y; s2 += e4.z;
                }
                unsigned om;
                asm volatile("ld.acquire.gpu.u32 %0, [%1];" : "=r"(om) : "l"(&g_mask));
                unsigned nm = om;
                float es[3] = {s0, s1, s2};
                for (int ch = 0; ch < 3; ch++) {
                    if (om & (1u << ch)) {
                        float err = es[ch] * (1.0f / (float)(BN*NP));
                        unsigned it = atomicAdd(&g_iter[ch], 1u) + 1u;
                        if (!(it < MAX_ITER && err >= THRESH)) nm &= ~(1u << ch);
                    }
                }
                atomicExch(&g_mask, nm);
                g_count = 0u;
                __threadfence();
                atomicAdd(&g_gen, 1u);
            } else {
                unsigned cur;
                do {
                    asm volatile("ld.acquire.gpu.u32 %0, [%1];" : "=r"(cur) : "l"(&g_gen));
                    if (cur < gen) __nanosleep(64);
                } while (cur < gen);
            }
            unsigned mk;
            asm volatile("ld.acquire.gpu.u32 %0, [%1];" : "=r"(mk) : "l"(&g_mask));
            s_mask = mk;
        }
        __syncthreads();
        mask = s_mask;
    }

    // OT contribution: sum r*c*K*sim with sim = 1 + eps*log(K)
    float ot = 0.f;
    for (int p = 0; p < 12; p++) {
        const float* Kp = &sK[p*SKP];
        const float* rp = &r_s[p*52];
        const float* cp = &c_s[p*80];
        for (int e = tid; e < NP*NT; e += STPB) {
            int n = e / NT, m = e - n*NT;
            float Kv = Kp[n*77 + m];
            float simv = fmaf(EPSI, logf(Kv), 1.0f);
            ot = fmaf(rp[n]*cp[m], Kv*simv, ot);
        }
    }
    red[tid] = ot;
    __syncthreads();
    for (int st = STPB/2; st > 0; st >>= 1) {
        if (tid < st) red[tid] += red[tid + st];
        __syncthreads();
    }
    if (tid == 0) g_ot_part[blk] = red[0];
}

// ---------------- logits GEMM: 512x512x2304, tf32, split-K=6 -----------------
// grid (8,8,6) = 384 blocks; each block: 64x64 tile over K-slice of 384 floats
// (12 chunks of 32), double-buffered smem, one __syncthreads per chunk.
// 8 warps (4m x 2n), warp tile m16n32 via 4 n8 frags, mma.m16n8k8 tf32.
__device__ __forceinline__ uint32_t f2tf(float x) {
    uint32_t r;
    asm("cvt.rna.tf32.f32 %0, %1;" : "=r"(r) : "f"(x));
    return r;
}

__global__ void __launch_bounds__(256) gemm_logits_tf32_kernel(
        const float* __restrict__ img, const float* __restrict__ txt) {
    __shared__ uint32_t As[2][64*36];   // [buf][row*36 + k], 32 data + 4 pad
    __shared__ uint32_t Bs[2][64*36];
    const int bx = blockIdx.x, by = blockIdx.y, bz = blockIdx.z;
    const int t = threadIdx.x;
    const int lane = t & 31, w = t >> 5;
    const int gid = lane >> 2, tig = lane & 3;
    const int wm = w >> 1, wn = w & 1;
    const int rowA = by * 64, rowB = bx * 64;
    const float4* A4 = reinterpret_cast<const float4*>(img);
    const float4* B4 = reinterpret_cast<const float4*>(txt);
    const int lr = t >> 2;       // 0..63 row within tile
    const int lj = t & 3;        // 0..3  k-quarter (8 floats each)
    const int kbase = bz * 96;   // float4 offset of this K slice (384 floats)

    float acc[4][4];
    #pragma unroll
    for (int f = 0; f < 4; f++) {
        acc[f][0] = 0.f; acc[f][1] = 0.f; acc[f][2] = 0.f; acc[f][3] = 0.f;
    }

    float4 va0, va1, vb0, vb1;
    auto gload = [&](int kc) {
        const size_t offA = (size_t)(rowA + lr)*576 + kbase + kc*8 + lj*2;
        const size_t offB = (size_t)(rowB + lr)*576 + kbase + kc*8 + lj*2;
        va0 = A4[offA]; va1 = A4[offA + 1];
        vb0 = B4[offB]; vb1 = B4[offB + 1];
    };
    auto sstore = [&](int buf) {
        uint4* pa = reinterpret_cast<uint4*>(&As[buf][lr*36 + lj*8]);
        uint4* pb = reinterpret_cast<uint4*>(&Bs[buf][lr*36 + lj*8]);
        pa[0] = make_uint4(f2tf(va0.x), f2tf(va0.y), f2tf(va0.z), f2tf(va0.w));
        pa[1] = make_uint4(f2tf(va1.x), f2tf(va1.y), f2tf(va1.z), f2tf(va1.w));
        pb[0] = make_uint4(f2tf(vb0.x), f2tf(vb0.y), f2tf(vb0.z), f2tf(vb0.w));
        pb[1] = make_uint4(f2tf(vb1.x), f2tf(vb1.y), f2tf(vb1.z), f2tf(vb1.w));
    };

    gload(0);
    sstore(0);
    __syncthreads();

    for (int kc = 0; kc < 12; kc++) {
        const int buf = kc & 1;
        if (kc < 11) gload(kc + 1);          // latency hidden under MMAs below
        #pragma unroll
        for (int ks = 0; ks < 4; ks++) {
            const int kw = ks * 8;
            uint32_t a0 = As[buf][(wm*16 + gid)*36 + kw + tig];
            uint32_t a1 = As[buf][(wm*16 + gid + 8)*36 + kw + tig];
            uint32_t a2 = As[buf][(wm*16 + gid)*36 + kw + 4 + tig];
            uint32_t a3 = As[buf][(wm*16 + gid + 8)*36 + kw + 4 + tig];
            #pragma unroll
            for (int f = 0; f < 4; f++) {
                int col = wn*32 + f*8 + gid;
                uint32_t b0 = Bs[buf][col*36 + kw + tig];
                uint32_t b1 = Bs[buf][col*36 + kw + 4 + tig];
                asm volatile(
                    "mma.sync.aligned.m16n8k8.row.col.f32.tf32.tf32.f32 "
                    "{%0,%1,%2,%3}, {%4,%5,%6,%7}, {%8,%9}, {%0,%1,%2,%3};"
                    : "+f"(acc[f][0]), "+f"(acc[f][1]), "+f"(acc[f][2]), "+f"(acc[f][3])
                    : "r"(a0), "r"(a1), "r"(a2), "r"(a3), "r"(b0), "r"(b1));
            }
        }
        if (kc < 11) sstore(1 - buf);        // other buffer: no conflict with reads
        __syncthreads();
    }

    float* out = g_Gp + (size_t)bz * BN * BN;
    const int r0 = rowA + wm*16 + gid;
    #pragma unroll
    for (int f = 0; f < 4; f++) {
        int col = rowB + wn*32 + f*8 + tig*2;
        *reinterpret_cast<float2*>(&out[(size_t)r0*BN + col]) =
            make_float2(acc[f][0], acc[f][1]);
        *reinterpret_cast<float2*>(&out[(size_t)(r0 + 8)*BN + col]) =
            make_float2(acc[f][2], acc[f][3]);
    }
}

__global__ void reduce_scale_kernel(const float* __restrict__ scale_p) {
    const size_t i = (size_t)blockIdx.x * 512 + threadIdx.x;
    const float s = scale_p[0] * (1.0f / (float)CC);
    float v = 0.f;
    #pragma unroll
    for (int j = 0; j < KSPLIT; j++) v += g_Gp[(size_t)j*BN*BN + i];
    g_L[i] = s * v;
}

// --------------------------- LSE + finalize ----------------------------------
__global__ void row_lse_kernel() {
    __shared__ float red[256];
    const int b = blockIdx.x, t = threadIdx.x;
    const float* row = g_L + (size_t)b * BN;
    float x0 = row[t], x1 = row[t + 256];
    red[t] = fmaxf(x0, x1);
    __syncthreads();
    for (int st = 128; st > 0; st >>= 1) {
        if (t < st) red[t] = fmaxf(red[t], red[t + st]);
        __syncthreads();
    }
    float M = red[0];
    __syncthreads();
    red[t] = expf(x0 - M) + expf(x1 - M);
    __syncthreads();
    for (int st = 128; st > 0; st >>= 1) {
        if (t < st) red[t] += red[t + st];
        __syncthreads();
    }
    if (t == 0) g_lse_row[b] = M + logf(red[0]);
}

__global__ void col_lse_kernel() {
    __shared__ float red[256];
    const int b = blockIdx.x, t = threadIdx.x;
    float x0 = g_L[(size_t)t * BN + b], x1 = g_L[(size_t)(t + 256) * BN + b];
    red[t] = fmaxf(x0, x1);
    __syncthreads();
    for (int st = 128; st > 0; st >>= 1) {
        if (t < st) red[t] = fmaxf(red[t], red[t + st]);
        __syncthreads();
    }
    float M = red[0];
    __syncthreads();
    red[t] = expf(x0 - M) + expf(x1 - M);
    __syncthreads();
    for (int st = 128; st > 0; st >>= 1) {
        if (t < st) red[t] += red[t + st];
        __syncthreads();
    }
    if (t == 0) g_lse_col[b] = M + logf(red[0]);
}

__global__ void finalize_kernel(float* __restrict__ out) {
    __shared__ float r1[512], r2[512], r3[512];
    const int t = threadIdx.x;
    float diag = g_L[(size_t)t * BN + t];
    r1[t] = g_lse_row[t] - diag;
    r2[t] = g_lse_col[t] - diag;
    r3[t] = (t < NBLK) ? g_ot_part[t] : 0.f;
    __syncthreads();
    for (int st = 256; st > 0; st >>= 1) {
        if (t < st) { r1[t] += r1[t+st]; r2[t] += r2[t+st]; r3[t] += r3[t+st]; }
        __syncthreads();
    }
    if (t == 0)
        out[0] = (r1[0] + r2[0]) * (0.5f / (float)BN) + r3[0];
}

// ------------------------------- launch --------------------------------------
extern "C" void kernel_launch(void* const* d_in, const int* in_sizes, int n_in,
                              void* d_out, int out_size) {
    (void)in_sizes; (void)n_in; (void)out_size;
    const float* img   = (const float*)d_in[0];
    const float* txt   = (const float*)d_in[1];
    const float* scale = (const float*)d_in[2];
    const float* li    = (const float*)d_in[3];
    const float* lt    = (const float*)d_in[4];
    float* out = (float*)d_out;

    const size_t sk_smem = (size_t)(12*SKP + 12*52 + 12*80 + 3*STPB) * sizeof(float);
    cudaFuncSetAttribute(sinkhorn_kernel,
                         cudaFuncAttributeMaxDynamicSharedMemorySize, (int)sk_smem);

    init_state_kernel<<<1, 1>>>();
    simK_kernel<<<BN*CC, 256>>>(li, lt);
    sinkhorn_kernel<<<NBLK, STPB, sk_smem>>>();
    dim3 gg(8, 8, KSPLIT);
    gemm_logits_tf32_kernel<<<gg, 256>>>(img, txt);
    reduce_scale_kernel<<<512, 512>>>(scale);
    row_lse_kernel<<<BN, 256>>>();
    col_lse_kernel<<<BN, 256>>>();
    finalize_kernel<<<1, 512>>>(out);
}

// round 9
// speedup vs baseline: 1.6168x; 1.2748x over previous
#include <cuda_runtime.h>
#include <cuda_bf16.h>
#include <cstdint>
#include <math.h>

#define BN 512
#define CC 3
#define NP 49
#define NT 76
#define DD 768
#define EPSI 0.1f
#define THRESH 0.01f
#define MAX_ITER 100

#define NBLK 128          // sinkhorn persistent blocks
#define STPB 512          // sinkhorn threads per block (16 warps)
#define SKP (49*77)       // padded K tile stride (3773 floats)
#define KSPLIT 6

// ------------------------- device scratch (no allocs allowed) ----------------
__device__ float g_K[(size_t)CC*BN*NP*NT];        // exp kernel per (c,b)
__device__ float g_Gp[(size_t)KSPLIT*BN*BN];      // split-K partials of logits GEMM
__device__ float g_L[(size_t)BN*BN];              // logits_per_image
__device__ float g_lse_row[BN];
__device__ float g_lse_col[BN];
__device__ float4 g_err4[NBLK];
__device__ float g_ot_part[NBLK];
__device__ unsigned g_count;
__device__ unsigned g_gen;
__device__ unsigned g_mask;

// --------------------- sim + K kernel (bf16 tensor cores) --------------------
// One block per (b,c). M=64 (49 real) x N=80 (76 real) x K=768.
// 8 warps: 4 (m) x 2 (n); warp tile m16 x 5 n8 frags, mma.m16n8k16 bf16.
// Double-buffered smem, ONE __syncthreads per k-chunk. fp32->bf16 conversion
// fused into the fill; row norms accumulated by fixed owner threads.
// Block 0 thread 0 also resets the sinkhorn cross-block state (runs before
// sinkhorn in stream order; required fresh on every graph replay).

__device__ __forceinline__ uint32_t pack_bf16(float x, float y) {
    __nv_bfloat162 h = __floats2bfloat162_rn(x, y);  // .x = low 16 bits
    return *reinterpret_cast<uint32_t*>(&h);
}

__global__ void __launch_bounds__(256) simK_kernel(const float* __restrict__ li,
                                                   const float* __restrict__ lt) {
    __shared__ uint32_t As32[2][64*20];   // row stride 20 words (16 data + 4 pad)
    __shared__ uint32_t Bs32[2][80*20];
    __shared__ float normA[64];
    __shared__ float normB[80];

    const int blk = blockIdx.x;        // b*3 + c
    const int b = blk / 3;
    const int c = blk - b*3;
    const float4* A4 = reinterpret_cast<const float4*>(li + ((size_t)(b*CC + c))*NP*DD);
    const float4* B4 = reinterpret_cast<const float4*>(lt + ((size_t)(b*CC + c))*NT*DD);

    const int t = threadIdx.x;
    const int lane = t & 31;
    const int w = t >> 5;
    const int gid = lane >> 2;          // 0..7
    const int tig = lane & 3;           // 0..3

    if (blk == 0 && t == 0) { g_count = 0u; g_gen = 0u; }   // sinkhorn state reset

    // fill roles: threads 0..97 -> A (row = t/2, half = t&1)
    //             threads 104..255 -> B (tb = t-104, row = tb/2, half = tb&1)
    const bool isA = (t < 98);
    const bool isB = (t >= 104);
    const int arow = t >> 1;
    const int tb = t - 104;
    const int brow = tb >> 1;
    const int q0A = (t & 1) * 4;
    const int q0B = (tb & 1) * 4;

    // zero norms + pad rows of BOTH buffers (written once, never overwritten)
    if (t < 64) normA[t] = 0.f;
    if (t >= 64 && t < 144) normB[t - 64] = 0.f;
    for (int e = t; e < (15 + 4) * 16 * 2; e += 256) {
        int bf = e & 1, e2 = e >> 1;
        int rr = e2 >> 4, ww = e2 & 15;
        if (rr < 15) As32[bf][(49 + rr)*20 + ww] = 0u;
        else         Bs32[bf][(76 + (rr - 15))*20 + ww] = 0u;
    }

    // warp tiling
    const int wm = w >> 1;              // 0..3
    const int wn = w & 1;               // 0..1
    const int r0 = wm*16 + gid;
    const int r1 = r0 + 8;

    float acc[5][4];
    #pragma unroll
    for (int f = 0; f < 5; f++) {
        acc[f][0] = 0.f; acc[f][1] = 0.f; acc[f][2] = 0.f; acc[f][3] = 0.f;
    }

    float4 rv[4];
    auto issue_load = [&](int kc) {
        if (isA) {
            const float4* src = A4 + arow*192 + kc*8 + q0A;
            #pragma unroll
            for (int i = 0; i < 4; i++) rv[i] = src[i];
        } else if (isB) {
            const float4* src = B4 + brow*192 + kc*8 + q0B;
            #pragma unroll
            for (int i = 0; i < 4; i++) rv[i] = src[i];
        }
    };
    auto store_tile = [&](int bf) {
        float ss = 0.f;
        if (isA) {
            #pragma unroll
            for (int i = 0; i < 4; i++) {
                float4 v = rv[i];
                ss += v.x*v.x + v.y*v.y + v.z*v.z + v.w*v.w;
                int wbase = arow*20 + (q0A + i)*2;
                As32[bf][wbase]     = pack_bf16(v.x, v.y);
                As32[bf][wbase + 1] = pack_bf16(v.z, v.w);
            }
        } else if (isB) {
            #pragma unroll
            for (int i = 0; i < 4; i++) {
                float4 v = rv[i];
                ss += v.x*v.x + v.y*v.y + v.z*v.z + v.w*v.w;
                int wbase = brow*20 + (q0B + i)*2;
                Bs32[bf][wbase]     = pack_bf16(v.x, v.y);
                Bs32[bf][wbase + 1] = pack_bf16(v.z, v.w);
            }
        }
        ss += __shfl_xor_sync(0xffffffffu, ss, 1);   // pair halves of a row
        if (isA && (t & 1) == 0) normA[arow] += ss;  // fixed owner -> deterministic
        if (isB && (tb & 1) == 0) normB[brow] += ss;
    };

    issue_load(0);
    store_tile(0);
    __syncthreads();

    for (int kc = 0; kc < 24; kc++) {
        const int bf = kc & 1;
        if (kc < 23) issue_load(kc + 1);   // latency hidden under MMAs
        #pragma unroll
        for (int ks = 0; ks < 2; ks++) {
            const int kw = ks * 8;
            uint32_t a0 = As32[bf][r0*20 + kw + tig];
            uint32_t a1 = As32[bf][r1*20 + kw + tig];
            uint32_t a2 = As32[bf][r0*20 + kw + 4 + tig];
            uint32_t a3 = As32[bf][r1*20 + kw + 4 + tig];
            #pragma unroll
            for (int f = 0; f < 5; f++) {
                int n = wn*40 + f*8 + gid;
                uint32_t b0 = Bs32[bf][n*20 + kw + tig];
                uint32_t b1 = Bs32[bf][n*20 + kw + 4 + tig];
                asm volatile(
                    "mma.sync.aligned.m16n8k16.row.col.f32.bf16.bf16.f32 "
                    "{%0,%1,%2,%3}, {%4,%5,%6,%7}, {%8,%9}, {%0,%1,%2,%3};"
                    : "+f"(acc[f][0]), "+f"(acc[f][1]), "+f"(acc[f][2]), "+f"(acc[f][3])
                    : "r"(a0), "r"(a1), "r"(a2), "r"(a3), "r"(b0), "r"(b1));
            }
        }
        if (kc < 23) store_tile(1 - bf);   // buffer read last iter; safe post-sync
        __syncthreads();
    }

    // ---- norms -> inverse norms (in place) ----
    if (t < 64)                normA[t]      = 1.0f / fmaxf(sqrtf(normA[t]), 1e-12f);
    if (t >= 64 && t < 144)    normB[t - 64] = 1.0f / fmaxf(sqrtf(normB[t - 64]), 1e-12f);
    __syncthreads();

    // ---- epilogue: sim -> K ----
    const size_t base = (size_t)(c*BN + b) * (NP*NT);
    const float ia0 = (r0 < NP) ? normA[r0] : 0.f;
    const float ia1 = (r1 < NP) ? normA[r1] : 0.f;
    #pragma unroll
    for (int f = 0; f < 5; f++) {
        int col = wn*40 + f*8 + tig*2;
        float ib0 = normB[col];
        float ib1 = normB[col + 1];
        if (col < NT) {
            if (r0 < NP) {
                float s0 = acc[f][0] * ia0 * ib0;
                float s1 = acc[f][1] * ia0 * ib1;
                g_K[base + (size_t)r0*NT + col] = expf(fmaf(10.0f, s0, -10.0f));
                if (col + 1 < NT)
                    g_K[base + (size_t)r0*NT + col + 1] = expf(fmaf(10.0f, s1, -10.0f));
            }
            if (r1 < NP) {
                float s2 = acc[f][2] * ia1 * ib0;
                float s3 = acc[f][3] * ia1 * ib1;
                g_K[base + (size_t)r1*NT + col] = expf(fmaf(10.0f, s2, -10.0f));
                if (col + 1 < NT)
                    g_K[base + (size_t)r1*NT + col + 1] = expf(fmaf(10.0f, s3, -10.0f));
            }
        }
    }
}

// ------------------------- persistent Sinkhorn kernel ------------------------
// 128 blocks x 16 warps; warp p (p<12) exclusively owns tile p (batch blk*4 +
// (p&3), channel p>>2): r/c updates are warp-local (no block syncs). Per
// iteration: 2 __syncthreads + 1 global sense-reversing barrier. Mask and
// per-channel iteration counters evolve in lockstep in EVERY block, so the
// master (last arriver; identity irrelevant — fixed reduce order) only
// publishes the global err verdict mask.
extern __shared__ float sh[];
__global__ void __launch_bounds__(STPB) sinkhorn_kernel() {
    float* sK  = sh;                       // 12*SKP
    float* r_s = sK + 12*SKP;              // 12*52
    float* c_s = r_s + 12*52;              // 12*80
    __shared__ float errw[12];
    __shared__ float warp_part[16];
    __shared__ unsigned s_mask;

    const int tid = threadIdx.x;
    const int blk = blockIdx.x;
    const int lane = tid & 31;
    const int w = tid >> 5;

    // load K tiles (padded stride 77)
    for (int p = 0; p < 12; p++) {
        int ch = p >> 2;
        int b  = blk*4 + (p & 3);
        const float* src = g_K + (size_t)(ch*BN + b) * (NP*NT);
        for (int e = tid; e < NP*NT; e += STPB) {
            int n = e / NT, m = e - n*NT;
            sK[p*SKP + n*77 + m] = src[e];
        }
    }
    for (int e = tid; e < 12*52; e += STPB) r_s[e] = 1.0f;
    for (int e = tid; e < 12*80; e += STPB) c_s[e] = 1.0f;
    __syncthreads();

    unsigned gen = 0;
    unsigned mask = 7u;
    int it0 = 0, it1 = 0, it2 = 0;          // lockstep in every block
    const float U = 1.0f / (float)NP;
    const float V = 1.0f / (float)NT;

    while (mask) {
        // ---- warp-local r and c updates ----
        if (w < 12) {
            const int p = w, ch = p >> 2;
            float epart = 0.f;
            if (mask & (1u << ch)) {
                const float* Kp = &sK[p*SKP];
                float* rp = &r_s[p*52];
                float* cp = &c_s[p*80];
                // r = u / (K c); rows lane, lane+32
                #pragma unroll
                for (int rr = 0; rr < 2; rr++) {
                    int n = lane + rr*32;
                    if (n < NP) {
                        const float* Kr = Kp + n*77;
                        float s = 0.f;
                        #pragma unroll 4
                        for (int m = 0; m < NT; m++) s = fmaf(Kr[m], cp[m], s);
                        float rn = U / s;
                        epart += fabsf(rn - rp[n]);
                        rp[n] = rn;
                    }
                }
                __syncwarp();
                // c = v / (K^T r); cols lane, +32, +64
                #pragma unroll
                for (int cc = 0; cc < 3; cc++) {
                    int m = lane + cc*32;
                    if (m < NT) {
                        const float* Kc = Kp + m;
                        const float* rr2 = rp;
                        float s = 0.f;
                        #pragma unroll 7
                        for (int n = 0; n < NP; n++) s = fmaf(Kc[n*77], rr2[n], s);
                        cp[m] = V / s;
                    }
                }
                // deterministic warp reduction of epart
                #pragma unroll
                for (int o = 16; o; o >>= 1)
                    epart += __shfl_xor_sync(0xffffffffu, epart, o);
            }
            if (lane == 0) errw[p] = epart;
        }
        __syncthreads();

        // ---- global barrier + verdict (warp 0) ----
        if (w == 0) {
            float e = (lane < 12) ? errw[lane] : 0.f;
            e += __shfl_xor_sync(0xffffffffu, e, 1);
            e += __shfl_xor_sync(0xffffffffu, e, 2);
            float s0 = __shfl_sync(0xffffffffu, e, 0);
            float s1 = __shfl_sync(0xffffffffu, e, 4);
            float s2 = __shfl_sync(0xffffffffu, e, 8);
            unsigned my = 0u;
            if (lane == 0) {
                g_err4[blk] = make_float4(s0, s1, s2, 0.f);
                __threadfence();
                my = atomicAdd(&g_count, 1u);
            }
            my = __shfl_sync(0xffffffffu, my, 0);
            gen++;
            if (my == NBLK - 1) {
                __threadfence();
                float a0 = 0.f, a1 = 0.f, a2 = 0.f;
                #pragma unroll
                for (int i2 = 0; i2 < 4; i2++) {
                    float4 e4 = __ldcg(&g_err4[lane*4 + i2]);
                    a0 += e4.x; a1 += e4.y; a2 += e4.z;
                }
                #pragma unroll
                for (int o = 16; o; o >>= 1) {
                    a0 += __shfl_xor_sync(0xffffffffu, a0, o);
                    a1 += __shfl_xor_sync(0xffffffffu, a1, o);
                    a2 += __shfl_xor_sync(0xffffffffu, a2, o);
                }
                if (lane == 0) {
                    unsigned nm = mask;
                    const float inv = 1.0f / (float)(BN*NP);
                    if (mask & 1u) { int it = it0 + 1;
                        if (!(it < MAX_ITER && a0*inv >= THRESH)) nm &= ~1u; }
                    if (mask & 2u) { int it = it1 + 1;
                        if (!(it < MAX_ITER && a1*inv >= THRESH)) nm &= ~2u; }
                    if (mask & 4u) { int it = it2 + 1;
                        if (!(it < MAX_ITER && a2*inv >= THRESH)) nm &= ~4u; }
                    atomicExch(&g_mask, nm);
                    g_count = 0u;
                    __threadfence();
                    atomicAdd(&g_gen, 1u);
                    s_mask = nm;
                }
            } else {
                if (lane == 0) {
                    unsigned cur;
                    do {
                        asm volatile("ld.acquire.gpu.u32 %0, [%1];"
                                     : "=r"(cur) : "l"(&g_gen));
                        if (cur < gen) __nanosleep(64);
                    } while (cur < gen);
                    unsigned mk;
                    asm volatile("ld.acquire.gpu.u32 %0, [%1];"
                                 : "=r"(mk) : "l"(&g_mask));
                    s_mask = mk;
                }
            }
        }
        __syncthreads();
        // lockstep iteration counters (all blocks identical)
        if (mask & 1u) it0++;
        if (mask & 2u) it1++;
        if (mask & 4u) it2++;
        mask = s_mask;
    }

    // ---- OT contribution: sum r*c*K*sim, sim = 1 + eps*log(K) ----
    float ot = 0.f;
    for (int p = 0; p < 12; p++) {
        const float* Kp = &sK[p*SKP];
        const float* rp = &r_s[p*52];
        const float* cp = &c_s[p*80];
        for (int e = tid; e < NP*NT; e += STPB) {
            int n = e / NT, m = e - n*NT;
            float Kv = Kp[n*77 + m];
            float simv = fmaf(EPSI, __logf(Kv), 1.0f);
            ot = fmaf(rp[n]*cp[m], Kv*simv, ot);
        }
    }
    #pragma unroll
    for (int o = 16; o; o >>= 1) ot += __shfl_xor_sync(0xffffffffu, ot, o);
    if (lane == 0) warp_part[w] = ot;
    __syncthreads();
    if (w == 0) {
        float v = (lane < 16) ? warp_part[lane] : 0.f;
        #pragma unroll
        for (int o = 8; o; o >>= 1) v += __shfl_xor_sync(0xffffffffu, v, o);
        if (lane == 0) g_ot_part[blk] = v;
    }
}

// ---------------- logits GEMM: 512x512x2304, tf32, split-K=6 -----------------
__device__ __forceinline__ uint32_t f2tf(float x) {
    uint32_t r;
    asm("cvt.rna.tf32.f32 %0, %1;" : "=r"(r) : "f"(x));
    return r;
}

__global__ void __launch_bounds__(256) gemm_logits_tf32_kernel(
        const float* __restrict__ img, const float* __restrict__ txt) {
    __shared__ uint32_t As[2][64*36];   // [buf][row*36 + k], 32 data + 4 pad
    __shared__ uint32_t Bs[2][64*36];
    const int bx = blockIdx.x, by = blockIdx.y, bz = blockIdx.z;
    const int t = threadIdx.x;
    const int lane = t & 31, w = t >> 5;
    const int gid = lane >> 2, tig = lane & 3;
    const int wm = w >> 1, wn = w & 1;
    const int rowA = by * 64, rowB = bx * 64;
    const float4* A4 = reinterpret_cast<const float4*>(img);
    const float4* B4 = reinterpret_cast<const float4*>(txt);
    const int lr = t >> 2;       // 0..63 row within tile
    const int lj = t & 3;        // 0..3  k-quarter (8 floats each)
    const int kbase = bz * 96;   // float4 offset of this K slice (384 floats)

    float acc[4][4];
    #pragma unroll
    for (int f = 0; f < 4; f++) {
        acc[f][0] = 0.f; acc[f][1] = 0.f; acc[f][2] = 0.f; acc[f][3] = 0.f;
    }

    float4 va0, va1, vb0, vb1;
    auto gload = [&](int kc) {
        const size_t offA = (size_t)(rowA + lr)*576 + kbase + kc*8 + lj*2;
        const size_t offB = (size_t)(rowB + lr)*576 + kbase + kc*8 + lj*2;
        va0 = A4[offA]; va1 = A4[offA + 1];
        vb0 = B4[offB]; vb1 = B4[offB + 1];
    };
    auto sstore = [&](int buf) {
        uint4* pa = reinterpret_cast<uint4*>(&As[buf][lr*36 + lj*8]);
        uint4* pb = reinterpret_cast<uint4*>(&Bs[buf][lr*36 + lj*8]);
        pa[0] = make_uint4(f2tf(va0.x), f2tf(va0.y), f2tf(va0.z), f2tf(va0.w));
        pa[1] = make_uint4(f2tf(va1.x), f2tf(va1.y), f2tf(va1.z), f2tf(va1.w));
        pb[0] = make_uint4(f2tf(vb0.x), f2tf(vb0.y), f2tf(vb0.z), f2tf(vb0.w));
        pb[1] = make_uint4(f2tf(vb1.x), f2tf(vb1.y), f2tf(vb1.z), f2tf(vb1.w));
    };

    gload(0);
    sstore(0);
    __syncthreads();

    for (int kc = 0; kc < 12; kc++) {
        const int buf = kc & 1;
        if (kc < 11) gload(kc + 1);          // latency hidden under MMAs below
        #pragma unroll
        for (int ks = 0; ks < 4; ks++) {
            const int kw = ks * 8;
            uint32_t a0 = As[buf][(wm*16 + gid)*36 + kw + tig];
            uint32_t a1 = As[buf][(wm*16 + gid + 8)*36 + kw + tig];
            uint32_t a2 = As[buf][(wm*16 + gid)*36 + kw + 4 + tig];
            uint32_t a3 = As[buf][(wm*16 + gid + 8)*36 + kw + 4 + tig];
            #pragma unroll
            for (int f = 0; f < 4; f++) {
                int col = wn*32 + f*8 + gid;
                uint32_t b0 = Bs[buf][col*36 + kw + tig];
                uint32_t b1 = Bs[buf][col*36 + kw + 4 + tig];
                asm volatile(
                    "mma.sync.aligned.m16n8k8.row.col.f32.tf32.tf32.f32 "
                    "{%0,%1,%2,%3}, {%4,%5,%6,%7}, {%8,%9}, {%0,%1,%2,%3};"
                    : "+f"(acc[f][0]), "+f"(acc[f][1]), "+f"(acc[f][2]), "+f"(acc[f][3])
                    : "r"(a0), "r"(a1), "r"(a2), "r"(a3), "r"(b0), "r"(b1));
            }
        }
        if (kc < 11) sstore(1 - buf);        // other buffer: no read conflict
        __syncthreads();
    }

    float* out = g_Gp + (size_t)bz * BN * BN;
    const int r0 = rowA + wm*16 + gid;
    #pragma unroll
    for (int f = 0; f < 4; f++) {
        int col = rowB + wn*32 + f*8 + tig*2;
        *reinterpret_cast<float2*>(&out[(size_t)r0*BN + col]) =
            make_float2(acc[f][0], acc[f][1]);
        *reinterpret_cast<float2*>(&out[(size_t)(r0 + 8)*BN + col]) =
            make_float2(acc[f][2], acc[f][3]);
    }
}

__global__ void reduce_scale_kernel(const float* __restrict__ scale_p) {
    const size_t i = (size_t)blockIdx.x * 512 + threadIdx.x;
    const float s = scale_p[0] * (1.0f / (float)CC);
    float v = 0.f;
    #pragma unroll
    for (int j = 0; j < KSPLIT; j++) v += g_Gp[(size_t)j*BN*BN + i];
    g_L[i] = s * v;
}

// --------------------------- LSE (rows + cols) + finalize --------------------
__global__ void lse_kernel() {
    __shared__ float red[256];
    const int gb = blockIdx.x;
    const int b = gb & (BN - 1);
    const bool isCol = gb >= BN;
    const int t = threadIdx.x;
    float x0, x1;
    if (!isCol) {
        const float* row = g_L + (size_t)b * BN;
        x0 = row[t]; x1 = row[t + 256];
    } else {
        x0 = g_L[(size_t)t * BN + b];
        x1 = g_L[(size_t)(t + 256) * BN + b];
    }
    red[t] = fmaxf(x0, x1);
    __syncthreads();
    for (int st = 128; st > 0; st >>= 1) {
        if (t < st) red[t] = fmaxf(red[t], red[t + st]);
        __syncthreads();
    }
    float M = red[0];
    __syncthreads();
    red[t] = expf(x0 - M) + expf(x1 - M);
    __syncthreads();
    for (int st = 128; st > 0; st >>= 1) {
        if (t < st) red[t] += red[t + st];
        __syncthreads();
    }
    if (t == 0) {
        float lse = M + logf(red[0]);
        if (!isCol) g_lse_row[b] = lse; else g_lse_col[b] = lse;
    }
}

__global__ void finalize_kernel(float* __restrict__ out) {
    __shared__ float r1[512], r2[512], r3[512];
    const int t = threadIdx.x;
    float diag = g_L[(size_t)t * BN + t];
    r1[t] = g_lse_row[t] - diag;
    r2[t] = g_lse_col[t] - diag;
    r3[t] = (t < NBLK) ? g_ot_part[t] : 0.f;
    __syncthreads();
    for (int st = 256; st > 0; st >>= 1) {
        if (t < st) { r1[t] += r1[t+st]; r2[t] += r2[t+st]; r3[t] += r3[t+st]; }
        __syncthreads();
    }
    if (t == 0)
        out[0] = (r1[0] + r2[0]) * (0.5f / (float)BN) + r3[0];
}

// ------------------------------- launch --------------------------------------
extern "C" void kernel_launch(void* const* d_in, const int* in_sizes, int n_in,
                              void* d_out, int out_size) {
    (void)in_sizes; (void)n_in; (void)out_size;
    const float* img   = (const float*)d_in[0];
    const float* txt   = (const float*)d_in[1];
    const float* scale = (const float*)d_in[2];
    const float* li    = (const float*)d_in[3];
    const float* lt    = (const float*)d_in[4];
    float* out = (float*)d_out;

    const size_t sk_smem = (size_t)(12*SKP + 12*52 + 12*80) * sizeof(float);
    cudaFuncSetAttribute(sinkhorn_kernel,
                         cudaFuncAttributeMaxDynamicSharedMemorySize, (int)sk_smem);

    simK_kernel<<<BN*CC, 256>>>(li, lt);
    sinkhorn_kernel<<<NBLK, STPB, sk_smem>>>();
    dim3 gg(8, 8, KSPLIT);
    gemm_logits_tf32_kernel<<<gg, 256>>>(img, txt);
    reduce_scale_kernel<<<512, 512>>>(scale);
    lse_kernel<<<2*BN, 256>>>();
    finalize_kernel<<<1, 512>>>(out);
}

// round 10
// speedup vs baseline: 1.6444x; 1.0171x over previous
#include <cuda_runtime.h>
#include <cuda_bf16.h>
#include <cstdint>
#include <math.h>

#define BN 512
#define CC 3
#define NP 49
#define NT 76
#define DD 768
#define EPSI 0.1f
#define THRESH 0.01f
#define MAX_ITER 100

#define NBLK 128          // sinkhorn persistent blocks
#define STPB 512          // sinkhorn threads per block (16 warps)
#define SKP (49*77)       // padded K tile stride (3773 floats)
#define KSPLIT 6
#define GEMM_BLKS 384     // 8 x 8 x 6 split-K tiles

// ------------------------- device scratch (no allocs allowed) ----------------
__device__ float g_K[(size_t)CC*BN*NP*NT];        // exp kernel per (c,b)
__device__ float g_Gp[(size_t)KSPLIT*BN*BN];      // split-K partials of logits GEMM
__device__ float g_L[(size_t)BN*BN];              // logits_per_image
__device__ float g_lse_row[BN];
__device__ float g_lse_col[BN];
__device__ float4 g_err4[NBLK];
__device__ float g_ot_part[NBLK];
__device__ unsigned g_count;
__device__ unsigned g_gen;
__device__ unsigned g_mask;
__device__ unsigned g_fin;

__device__ __forceinline__ uint32_t pack_bf16(float x, float y) {
    __nv_bfloat162 h = __floats2bfloat162_rn(x, y);  // .x = low 16 bits
    return *reinterpret_cast<uint32_t*>(&h);
}
__device__ __forceinline__ uint32_t f2tf(float x) {
    uint32_t r;
    asm("cvt.rna.tf32.f32 %0, %1;" : "=r"(r) : "f"(x));
    return r;
}

// ---------------- fused kernel: logits GEMM (blocks 0..383) ------------------
//                + simK        (blocks 384..1919)
// The two halves are independent (img/txt vs li/lt) and have complementary
// bottlenecks (tensor/smem vs DRAM): grid-union overlaps them in one wavefront.

__device__ void gemm_part(uint32_t* smem, int g,
                          const float* __restrict__ img,
                          const float* __restrict__ txt) {
    // dynamic smem layout: As [2][64*36] then Bs [2][64*36] (words)
    uint32_t* As = smem;            // 4608 words
    uint32_t* Bs = smem + 4608;     // 4608 words
    const int bz = g >> 6;
    const int by = (g & 63) >> 3;
    const int bx = g & 7;
    const int t = threadIdx.x;
    const int lane = t & 31, w = t >> 5;
    const int gid = lane >> 2, tig = lane & 3;
    const int wm = w >> 1, wn = w & 1;
    const int rowA = by * 64, rowB = bx * 64;
    const float4* A4 = reinterpret_cast<const float4*>(img);
    const float4* B4 = reinterpret_cast<const float4*>(txt);
    const int lr = t >> 2;       // 0..63 row within tile
    const int lj = t & 3;        // 0..3  k-quarter (8 floats each)
    const int kbase = bz * 96;   // float4 offset of this K slice

    float acc[4][4];
    #pragma unroll
    for (int f = 0; f < 4; f++) {
        acc[f][0] = 0.f; acc[f][1] = 0.f; acc[f][2] = 0.f; acc[f][3] = 0.f;
    }

    float4 va0, va1, vb0, vb1;
    auto gload = [&](int kc) {
        const size_t offA = (size_t)(rowA + lr)*576 + kbase + kc*8 + lj*2;
        const size_t offB = (size_t)(rowB + lr)*576 + kbase + kc*8 + lj*2;
        va0 = A4[offA]; va1 = A4[offA + 1];
        vb0 = B4[offB]; vb1 = B4[offB + 1];
    };
    auto sstore = [&](int buf) {
        uint4* pa = reinterpret_cast<uint4*>(&As[buf*4608/2 + lr*36 + lj*8]);
        uint4* pb = reinterpret_cast<uint4*>(&Bs[buf*4608/2 + lr*36 + lj*8]);
        pa[0] = make_uint4(f2tf(va0.x), f2tf(va0.y), f2tf(va0.z), f2tf(va0.w));
        pa[1] = make_uint4(f2tf(va1.x), f2tf(va1.y), f2tf(va1.z), f2tf(va1.w));
        pb[0] = make_uint4(f2tf(vb0.x), f2tf(vb0.y), f2tf(vb0.z), f2tf(vb0.w));
        pb[1] = make_uint4(f2tf(vb1.x), f2tf(vb1.y), f2tf(vb1.z), f2tf(vb1.w));
    };

    gload(0);
    sstore(0);
    __syncthreads();

    for (int kc = 0; kc < 12; kc++) {
        const int buf = kc & 1;
        const uint32_t* Ab = &As[buf*2304];
        const uint32_t* Bb = &Bs[buf*2304];
        if (kc < 11) gload(kc + 1);          // latency hidden under MMAs
        #pragma unroll
        for (int ks = 0; ks < 4; ks++) {
            const int kw = ks * 8;
            uint32_t a0 = Ab[(wm*16 + gid)*36 + kw + tig];
            uint32_t a1 = Ab[(wm*16 + gid + 8)*36 + kw + tig];
            uint32_t a2 = Ab[(wm*16 + gid)*36 + kw + 4 + tig];
            uint32_t a3 = Ab[(wm*16 + gid + 8)*36 + kw + 4 + tig];
            #pragma unroll
            for (int f = 0; f < 4; f++) {
                int col = wn*32 + f*8 + gid;
                uint32_t b0 = Bb[col*36 + kw + tig];
                uint32_t b1 = Bb[col*36 + kw + 4 + tig];
                asm volatile(
                    "mma.sync.aligned.m16n8k8.row.col.f32.tf32.tf32.f32 "
                    "{%0,%1,%2,%3}, {%4,%5,%6,%7}, {%8,%9}, {%0,%1,%2,%3};"
                    : "+f"(acc[f][0]), "+f"(acc[f][1]), "+f"(acc[f][2]), "+f"(acc[f][3])
                    : "r"(a0), "r"(a1), "r"(a2), "r"(a3), "r"(b0), "r"(b1));
            }
        }
        if (kc < 11) sstore(1 - buf);
        __syncthreads();
    }

    float* out = g_Gp + (size_t)bz * BN * BN;
    const int r0 = rowA + wm*16 + gid;
    #pragma unroll
    for (int f = 0; f < 4; f++) {
        int col = rowB + wn*32 + f*8 + tig*2;
        *reinterpret_cast<float2*>(&out[(size_t)r0*BN + col]) =
            make_float2(acc[f][0], acc[f][1]);
        *reinterpret_cast<float2*>(&out[(size_t)(r0 + 8)*BN + col]) =
            make_float2(acc[f][2], acc[f][3]);
    }
}

__device__ void simK_part(uint32_t* smem, int blk,
                          const float* __restrict__ li,
                          const float* __restrict__ lt) {
    // dynamic smem layout (words): As32 [2][64*20], Bs32 [2][80*20],
    // normA [64], normB [80]
    uint32_t* As32 = smem;                    // 2560 words
    uint32_t* Bs32 = smem + 2560;             // 3200 words
    float* normA = reinterpret_cast<float*>(smem + 5760);
    float* normB = normA + 64;

    const int b = blk / 3;
    const int c = blk - b*3;
    const float4* A4 = reinterpret_cast<const float4*>(li + ((size_t)(b*CC + c))*NP*DD);
    const float4* B4 = reinterpret_cast<const float4*>(lt + ((size_t)(b*CC + c))*NT*DD);

    const int t = threadIdx.x;
    const int lane = t & 31;
    const int w = t >> 5;
    const int gid = lane >> 2;
    const int tig = lane & 3;

    const bool isA = (t < 98);
    const bool isB = (t >= 104);
    const int arow = t >> 1;
    const int tb = t - 104;
    const int brow = tb >> 1;
    const int q0A = (t & 1) * 4;
    const int q0B = (tb & 1) * 4;

    if (t < 64) normA[t] = 0.f;
    if (t >= 64 && t < 144) normB[t - 64] = 0.f;
    for (int e = t; e < (15 + 4) * 16 * 2; e += 256) {
        int bf = e & 1, e2 = e >> 1;
        int rr = e2 >> 4, ww = e2 & 15;
        if (rr < 15) As32[bf*1280 + (49 + rr)*20 + ww] = 0u;
        else         Bs32[bf*1600 + (76 + (rr - 15))*20 + ww] = 0u;
    }

    const int wm = w >> 1;
    const int wn = w & 1;
    const int r0 = wm*16 + gid;
    const int r1 = r0 + 8;

    float acc[5][4];
    #pragma unroll
    for (int f = 0; f < 5; f++) {
        acc[f][0] = 0.f; acc[f][1] = 0.f; acc[f][2] = 0.f; acc[f][3] = 0.f;
    }

    float4 rv[4];
    auto issue_load = [&](int kc) {
        if (isA) {
            const float4* src = A4 + arow*192 + kc*8 + q0A;
            #pragma unroll
            for (int i = 0; i < 4; i++) rv[i] = src[i];
        } else if (isB) {
            const float4* src = B4 + brow*192 + kc*8 + q0B;
            #pragma unroll
            for (int i = 0; i < 4; i++) rv[i] = src[i];
        }
    };
    auto store_tile = [&](int bf) {
        float ss = 0.f;
        if (isA) {
            #pragma unroll
            for (int i = 0; i < 4; i++) {
                float4 v = rv[i];
                ss += v.x*v.x + v.y*v.y + v.z*v.z + v.w*v.w;
                int wbase = bf*1280 + arow*20 + (q0A + i)*2;
                As32[wbase]     = pack_bf16(v.x, v.y);
                As32[wbase + 1] = pack_bf16(v.z, v.w);
            }
        } else if (isB) {
            #pragma unroll
            for (int i = 0; i < 4; i++) {
                float4 v = rv[i];
                ss += v.x*v.x + v.y*v.y + v.z*v.z + v.w*v.w;
                int wbase = bf*1600 + brow*20 + (q0B + i)*2;
                Bs32[wbase]     = pack_bf16(v.x, v.y);
                Bs32[wbase + 1] = pack_bf16(v.z, v.w);
            }
        }
        ss += __shfl_xor_sync(0xffffffffu, ss, 1);
        if (isA && (t & 1) == 0) normA[arow] += ss;
        if (isB && (tb & 1) == 0) normB[brow] += ss;
    };

    issue_load(0);
    store_tile(0);
    __syncthreads();

    for (int kc = 0; kc < 24; kc++) {
        const int bf = kc & 1;
        if (kc < 23) issue_load(kc + 1);
        #pragma unroll
        for (int ks = 0; ks < 2; ks++) {
            const int kw = ks * 8;
            uint32_t a0 = As32[bf*1280 + r0*20 + kw + tig];
            uint32_t a1 = As32[bf*1280 + r1*20 + kw + tig];
            uint32_t a2 = As32[bf*1280 + r0*20 + kw + 4 + tig];
            uint32_t a3 = As32[bf*1280 + r1*20 + kw + 4 + tig];
            #pragma unroll
            for (int f = 0; f < 5; f++) {
                int n = wn*40 + f*8 + gid;
                uint32_t b0 = Bs32[bf*1600 + n*20 + kw + tig];
                uint32_t b1 = Bs32[bf*1600 + n*20 + kw + 4 + tig];
                asm volatile(
                    "mma.sync.aligned.m16n8k16.row.col.f32.bf16.bf16.f32 "
                    "{%0,%1,%2,%3}, {%4,%5,%6,%7}, {%8,%9}, {%0,%1,%2,%3};"
                    : "+f"(acc[f][0]), "+f"(acc[f][1]), "+f"(acc[f][2]), "+f"(acc[f][3])
                    : "r"(a0), "r"(a1), "r"(a2), "r"(a3), "r"(b0), "r"(b1));
            }
        }
        if (kc < 23) store_tile(1 - bf);
        __syncthreads();
    }

    if (t < 64)                normA[t]      = 1.0f / fmaxf(sqrtf(normA[t]), 1e-12f);
    if (t >= 64 && t < 144)    normB[t - 64] = 1.0f / fmaxf(sqrtf(normB[t - 64]), 1e-12f);
    __syncthreads();

    const size_t base = (size_t)(c*BN + b) * (NP*NT);
    const float ia0 = (r0 < NP) ? normA[r0] : 0.f;
    const float ia1 = (r1 < NP) ? normA[r1] : 0.f;
    #pragma unroll
    for (int f = 0; f < 5; f++) {
        int col = wn*40 + f*8 + tig*2;
        float ib0 = normB[col];
        float ib1 = normB[col + 1];
        if (col < NT) {
            if (r0 < NP) {
                float s0 = acc[f][0] * ia0 * ib0;
                float s1 = acc[f][1] * ia0 * ib1;
                g_K[base + (size_t)r0*NT + col] = expf(fmaf(10.0f, s0, -10.0f));
                if (col + 1 < NT)
                    g_K[base + (size_t)r0*NT + col + 1] = expf(fmaf(10.0f, s1, -10.0f));
            }
            if (r1 < NP) {
                float s2 = acc[f][2] * ia1 * ib0;
                float s3 = acc[f][3] * ia1 * ib1;
                g_K[base + (size_t)r1*NT + col] = expf(fmaf(10.0f, s2, -10.0f));
                if (col + 1 < NT)
                    g_K[base + (size_t)r1*NT + col + 1] = expf(fmaf(10.0f, s3, -10.0f));
            }
        }
    }
}

extern __shared__ uint32_t dynsmem[];
__global__ void __launch_bounds__(256) fused_simK_gemm_kernel(
        const float* __restrict__ li, const float* __restrict__ lt,
        const float* __restrict__ img, const float* __restrict__ txt) {
    if (blockIdx.x == 0 && threadIdx.x == 0) {
        g_count = 0u; g_gen = 0u; g_fin = 0u;   // fresh per graph replay
    }
    if (blockIdx.x < GEMM_BLKS) gemm_part(dynsmem, blockIdx.x, img, txt);
    else                        simK_part(dynsmem, blockIdx.x - GEMM_BLKS, li, lt);
}

// ------------------------- persistent Sinkhorn kernel ------------------------
// (unchanged from R9: 128 blocks x 16 warps, warp-owned tiles, lockstep mask)
extern __shared__ float sh[];
__global__ void __launch_bounds__(STPB) sinkhorn_kernel() {
    float* sK  = sh;                       // 12*SKP
    float* r_s = sK + 12*SKP;              // 12*52
    float* c_s = r_s + 12*52;              // 12*80
    __shared__ float errw[12];
    __shared__ float warp_part[16];
    __shared__ unsigned s_mask;

    const int tid = threadIdx.x;
    const int blk = blockIdx.x;
    const int lane = tid & 31;
    const int w = tid >> 5;

    for (int p = 0; p < 12; p++) {
        int ch = p >> 2;
        int b  = blk*4 + (p & 3);
        const float* src = g_K + (size_t)(ch*BN + b) * (NP*NT);
        for (int e = tid; e < NP*NT; e += STPB) {
            int n = e / NT, m = e - n*NT;
            sK[p*SKP + n*77 + m] = src[e];
        }
    }
    for (int e = tid; e < 12*52; e += STPB) r_s[e] = 1.0f;
    for (int e = tid; e < 12*80; e += STPB) c_s[e] = 1.0f;
    __syncthreads();

    unsigned gen = 0;
    unsigned mask = 7u;
    int it0 = 0, it1 = 0, it2 = 0;
    const float U = 1.0f / (float)NP;
    const float V = 1.0f / (float)NT;

    while (mask) {
        if (w < 12) {
            const int p = w, ch = p >> 2;
            float epart = 0.f;
            if (mask & (1u << ch)) {
                const float* Kp = &sK[p*SKP];
                float* rp = &r_s[p*52];
                float* cp = &c_s[p*80];
                #pragma unroll
                for (int rr = 0; rr < 2; rr++) {
                    int n = lane + rr*32;
                    if (n < NP) {
                        const float* Kr = Kp + n*77;
                        float s = 0.f;
                        #pragma unroll 4
                        for (int m = 0; m < NT; m++) s = fmaf(Kr[m], cp[m], s);
                        float rn = U / s;
                        epart += fabsf(rn - rp[n]);
                        rp[n] = rn;
                    }
                }
                __syncwarp();
                #pragma unroll
                for (int cc = 0; cc < 3; cc++) {
                    int m = lane + cc*32;
                    if (m < NT) {
                        const float* Kc = Kp + m;
                        float s = 0.f;
                        #pragma unroll 7
                        for (int n = 0; n < NP; n++) s = fmaf(Kc[n*77], rp[n], s);
                        cp[m] = V / s;
                    }
                }
                #pragma unroll
                for (int o = 16; o; o >>= 1)
                    epart += __shfl_xor_sync(0xffffffffu, epart, o);
            }
            if (lane == 0) errw[p] = epart;
        }
        __syncthreads();

        if (w == 0) {
            float e = (lane < 12) ? errw[lane] : 0.f;
            e += __shfl_xor_sync(0xffffffffu, e, 1);
            e += __shfl_xor_sync(0xffffffffu, e, 2);
            float s0 = __shfl_sync(0xffffffffu, e, 0);
            float s1 = __shfl_sync(0xffffffffu, e, 4);
            float s2 = __shfl_sync(0xffffffffu, e, 8);
            unsigned my = 0u;
            if (lane == 0) {
                g_err4[blk] = make_float4(s0, s1, s2, 0.f);
                __threadfence();
                my = atomicAdd(&g_count, 1u);
            }
            my = __shfl_sync(0xffffffffu, my, 0);
            gen++;
            if (my == NBLK - 1) {
                __threadfence();
                float a0 = 0.f, a1 = 0.f, a2 = 0.f;
                #pragma unroll
                for (int i2 = 0; i2 < 4; i2++) {
                    float4 e4 = __ldcg(&g_err4[lane*4 + i2]);
                    a0 += e4.x; a1 += e4.y; a2 += e4.z;
                }
                #pragma unroll
                for (int o = 16; o; o >>= 1) {
                    a0 += __shfl_xor_sync(0xffffffffu, a0, o);
                    a1 += __shfl_xor_sync(0xffffffffu, a1, o);
                    a2 += __shfl_xor_sync(0xffffffffu, a2, o);
                }
                if (lane == 0) {
                    unsigned nm = mask;
                    const float inv = 1.0f / (float)(BN*NP);
                    if (mask & 1u) { int it = it0 + 1;
                        if (!(it < MAX_ITER && a0*inv >= THRESH)) nm &= ~1u; }
                    if (mask & 2u) { int it = it1 + 1;
                        if (!(it < MAX_ITER && a1*inv >= THRESH)) nm &= ~2u; }
                    if (mask & 4u) { int it = it2 + 1;
                        if (!(it < MAX_ITER && a2*inv >= THRESH)) nm &= ~4u; }
                    atomicExch(&g_mask, nm);
                    g_count = 0u;
                    __threadfence();
                    atomicAdd(&g_gen, 1u);
                    s_mask = nm;
                }
            } else {
                if (lane == 0) {
                    unsigned cur;
                    do {
                        asm volatile("ld.acquire.gpu.u32 %0, [%1];"
                                     : "=r"(cur) : "l"(&g_gen));
                        if (cur < gen) __nanosleep(64);
                    } while (cur < gen);
                    unsigned mk;
                    asm volatile("ld.acquire.gpu.u32 %0, [%1];"
                                 : "=r"(mk) : "l"(&g_mask));
                    s_mask = mk;
                }
            }
        }
        __syncthreads();
        if (mask & 1u) it0++;
        if (mask & 2u) it1++;
        if (mask & 4u) it2++;
        mask = s_mask;
    }

    // OT contribution: sum r*c*K*sim, sim = 1 + eps*log(K)
    float ot = 0.f;
    for (int p = 0; p < 12; p++) {
        const float* Kp = &sK[p*SKP];
        const float* rp = &r_s[p*52];
        const float* cp = &c_s[p*80];
        for (int e = tid; e < NP*NT; e += STPB) {
            int n = e / NT, m = e - n*NT;
            float Kv = Kp[n*77 + m];
            float simv = fmaf(EPSI, __logf(Kv), 1.0f);
            ot = fmaf(rp[n]*cp[m], Kv*simv, ot);
        }
    }
    #pragma unroll
    for (int o = 16; o; o >>= 1) ot += __shfl_xor_sync(0xffffffffu, ot, o);
    if (lane == 0) warp_part[w] = ot;
    __syncthreads();
    if (w == 0) {
        float v = (lane < 16) ? warp_part[lane] : 0.f;
        #pragma unroll
        for (int o = 8; o; o >>= 1) v += __shfl_xor_sync(0xffffffffu, v, o);
        if (lane == 0) g_ot_part[blk] = v;
    }
}

// ---------------- row pass: split-K reduce + scale + row LSE -----------------
__global__ void rowlse_kernel(const float* __restrict__ scale_p) {
    __shared__ float red[256];
    const int b = blockIdx.x, t = threadIdx.x;
    const float s = scale_p[0] * (1.0f / (float)CC);
    float x0 = 0.f, x1 = 0.f;
    #pragma unroll
    for (int j = 0; j < KSPLIT; j++) {
        const float* row = g_Gp + (size_t)j*BN*BN + (size_t)b*BN;
        x0 += row[t];
        x1 += row[t + 256];
    }
    x0 *= s; x1 *= s;
    g_L[(size_t)b*BN + t] = x0;
    g_L[(size_t)b*BN + t + 256] = x1;

    red[t] = fmaxf(x0, x1);
    __syncthreads();
    for (int st = 128; st > 0; st >>= 1) {
        if (t < st) red[t] = fmaxf(red[t], red[t + st]);
        __syncthreads();
    }
    float M = red[0];
    __syncthreads();
    red[t] = expf(x0 - M) + expf(x1 - M);
    __syncthreads();
    for (int st = 128; st > 0; st >>= 1) {
        if (t < st) red[t] += red[t + st];
        __syncthreads();
    }
    if (t == 0) g_lse_row[b] = M + logf(red[0]);
}

// ---------------- col pass: col LSE + last-block finalize --------------------
__global__ void collse_fin_kernel(float* __restrict__ out) {
    __shared__ float red[256];
    __shared__ unsigned isLast;
    const int cidx = blockIdx.x, t = threadIdx.x;
    float x0 = g_L[(size_t)t * BN + cidx];
    float x1 = g_L[(size_t)(t + 256) * BN + cidx];
    red[t] = fmaxf(x0, x1);
    __syncthreads();
    for (int st = 128; st > 0; st >>= 1) {
        if (t < st) red[t] = fmaxf(red[t], red[t + st]);
        __syncthreads();
    }
    float M = red[0];
    __syncthreads();
    red[t] = expf(x0 - M) + expf(x1 - M);
    __syncthreads();
    for (int st = 128; st > 0; st >>= 1) {
        if (t < st) red[t] += red[t + st];
        __syncthreads();
    }
    if (t == 0) {
        g_lse_col[cidx] = M + logf(red[0]);
        __threadfence();
        isLast = (atomicAdd(&g_fin, 1u) == (unsigned)(BN - 1));
    }
    __syncthreads();
    if (isLast) {
        __threadfence();
        // deterministic: fixed-order reduction, independent of which block runs it
        __shared__ float r1[256], r2[256], r3[256];
        float a1 = 0.f, a2 = 0.f, a3 = 0.f;
        #pragma unroll
        for (int h = 0; h < 2; h++) {
            int i = t + h*256;
            float diag = __ldcg(&g_L[(size_t)i * BN + i]);
            a1 += __ldcg(&g_lse_row[i]) - diag;
            a2 += __ldcg(&g_lse_col[i]) - diag;
            if (i < NBLK) a3 += __ldcg(&g_ot_part[i]);
        }
        r1[t] = a1; r2[t] = a2; r3[t] = a3;
        __syncthreads();
        for (int st = 128; st > 0; st >>= 1) {
            if (t < st) { r1[t] += r1[t+st]; r2[t] += r2[t+st]; r3[t] += r3[t+st]; }
            __syncthreads();
        }
        if (t == 0)
            out[0] = (r1[0] + r2[0]) * (0.5f / (float)BN) + r3[0];
    }
}

// ------------------------------- launch --------------------------------------
extern "C" void kernel_launch(void* const* d_in, const int* in_sizes, int n_in,
                              void* d_out, int out_size) {
    (void)in_sizes; (void)n_in; (void)out_size;
    const float* img   = (const float*)d_in[0];
    const float* txt   = (const float*)d_in[1];
    const float* scale = (const float*)d_in[2];
    const float* li    = (const float*)d_in[3];
    const float* lt    = (const float*)d_in[4];
    float* out = (float*)d_out;

    const size_t fused_smem = 9216 * sizeof(uint32_t);   // 36864 B (gemm side max)
    const size_t sk_smem = (size_t)(12*SKP + 12*52 + 12*80) * sizeof(float);
    cudaFuncSetAttribute(sinkhorn_kernel,
                         cudaFuncAttributeMaxDynamicSharedMemorySize, (int)sk_smem);

    fused_simK_gemm_kernel<<<GEMM_BLKS + BN*CC, 256, fused_smem>>>(li, lt, img, txt);
    sinkhorn_kernel<<<NBLK, STPB, sk_smem>>>();
    rowlse_kernel<<<BN, 256>>>(scale);
    collse_fin_kernel<<<BN, 256>>>(out);
}